// round 14
// baseline (speedup 1.0000x reference)
#include <cuda_runtime.h>
#include <cstdint>

// ---------------------------------------------------------------------------
// FrameConsistencyLoss, single persistent kernel.
//
// Prologue (per CTA, redundant, conflict-free): stage W (row-padded, stride
// 65) + bias; 10 expert-level Grams G(x,y)=W_x W_y^T; assemble 16 pair
// matrices M M^T from G blocks; per-warp Cholesky + solve + packed table.
// Main loop: cp.async double-buffered 768-row tiles; histogram + counting
// sort by (ea,eb); warps process pair-uniform 64-row fused items with STATIC
// striding (next-item metadata prefetchable); rows read from staged smem.
//
// L_row(off-diag) = || C^T w + d ||^2 + s'   (w=[a;b], C = chol(M M^T))
// L_row(diag)     = || C14^T (a-b) ||^2
// ---------------------------------------------------------------------------

#define TILE   768
#define NTHR   512
#define NWARP  16
#define MAXW   28

// table layout in ULLs
#define OFF_ULL   224
#define DIAG_BASE 2688
#define DIAG_ULL  56
#define SPRIME_U  2912
#define TAB_U     2920

#define ROW_B     56                      // bytes per row (14 floats)
#define HALF_B    (TILE * ROW_B)          // one array (A or B) per slot
#define BUF_SLOT  (2 * HALF_B)            // A then B

typedef unsigned long long ull;

__device__ double g_sum;
__device__ int    g_done;

__device__ const int PX[10] = {0,0,0,0,1,1,1,2,2,3};
__device__ const int PY[10] = {0,1,2,3,1,2,3,2,3,3};

__device__ __forceinline__ int qidx(int x, int y) {   // x <= y
    return 4 * x - (x * (x - 1)) / 2 + (y - x);
}

__device__ __forceinline__ ull pk2(float lo, float hi) {
    ull r; asm("mov.b64 %0, {%1,%2};" : "=l"(r) : "f"(lo), "f"(hi)); return r;
}
__device__ __forceinline__ void upk2(ull v, float& lo, float& hi) {
    asm("mov.b64 {%0,%1}, %2;" : "=f"(lo), "=f"(hi) : "l"(v));
}
__device__ __forceinline__ ull ffma2(ull a, ull b, ull c) {
    ull d; asm("fma.rn.f32x2 %0, %1, %2, %3;" : "=l"(d) : "l"(a), "l"(b), "l"(c)); return d;
}
__device__ __forceinline__ uint32_t smem_u32(const void* p) {
    uint32_t a;
    asm("{ .reg .u64 t; cvta.to.shared.u64 t, %1; cvt.u32.u64 %0, t; }" : "=r"(a) : "l"(p));
    return a;
}
__device__ __forceinline__ void cp16(uint32_t s, const void* g) {
    asm volatile("cp.async.cg.shared.global [%0], [%1], 16;" :: "r"(s), "l"(g));
}
__device__ __forceinline__ void cp8(uint32_t s, const void* g) {
    asm volatile("cp.async.ca.shared.global [%0], [%1], 8;" :: "r"(s), "l"(g));
}

__device__ __forceinline__ int frow(int j) {       // ulls in C-rows 0..j-1
    int q = j >> 1, r = j & 1;
    return j + q * (q - 1) + r * q;
}

struct Pro {
    float Wst[56 * 65];        // W rows, stride 65 (bank-conflict-free)
    float Bst[4 * 64];
    float Ge[10 * 14 * 15];    // expert Grams, row stride 15
    float C[16][28][29];       // assembled M M^T -> Cholesky scratch
    float Mc[16][28];
    float cc[16];
};

struct Smem {
    ull tab[TAB_U];
    union {
        Pro  pro;
        char buf[2][BUF_SLOT];
    } u;
    int   order[TILE];
    int   count[16];
    int   ofs[16];
    int   wP[MAXW], wO[MAXW], wN[MAXW];
    int   num;
    float red[NWARP];
};

// ---------------------------------------------------------------------------
// evaluation (pack-over-k; fused variant shares table LDS across 2 row sets)
// ---------------------------------------------------------------------------
template<bool FUSED>
__device__ __forceinline__ float eval_off(const ull* __restrict__ T, float sp,
    const ull* __restrict__ A1, const ull* __restrict__ B1,
    const ull* __restrict__ A2, const ull* __restrict__ B2,
    bool v1, bool v2)
{
    ull S1[14], S2[14];
#pragma unroll
    for (int k = 0; k < 14; k++) { S1[k] = T[k]; if (FUSED) S2[k] = T[k]; }
    int idx = 14;
#pragma unroll
    for (int jj = 0; jj < 14; jj++) {
        ull w1 = (jj < 7) ? A1[jj] : B1[jj - 7];
        float lo1, hi1; upk2(w1, lo1, hi1);
        ull bl1 = pk2(lo1, lo1), bh1 = pk2(hi1, hi1);
        ull bl2 = 0, bh2 = 0;
        if (FUSED) {
            ull w2 = (jj < 7) ? A2[jj] : B2[jj - 7];
            float lo2, hi2; upk2(w2, lo2, hi2);
            bl2 = pk2(lo2, lo2); bh2 = pk2(hi2, hi2);
        }
#pragma unroll
        for (int kk = 0; kk <= jj; kk++) {
            ull t = T[idx + kk];
            S1[kk] = ffma2(t, bl1, S1[kk]);
            if (FUSED) S2[kk] = ffma2(t, bl2, S2[kk]);
        }
#pragma unroll
        for (int kk = 0; kk <= jj; kk++) {
            ull t = T[idx + jj + 1 + kk];
            S1[kk] = ffma2(t, bh1, S1[kk]);
            if (FUSED) S2[kk] = ffma2(t, bh2, S2[kk]);
        }
        idx += 2 * (jj + 1);
    }
    float L1 = sp, L2 = sp;
#pragma unroll
    for (int k = 0; k < 14; k++) {
        float lo, hi;
        upk2(S1[k], lo, hi); L1 = fmaf(lo, lo, L1); L1 = fmaf(hi, hi, L1);
        if (FUSED) { upk2(S2[k], lo, hi); L2 = fmaf(lo, lo, L2); L2 = fmaf(hi, hi, L2); }
    }
    float r = v1 ? L1 : 0.f;
    if (FUSED) r += v2 ? L2 : 0.f;
    return r;
}

template<bool FUSED>
__device__ __forceinline__ float eval_diag(const ull* __restrict__ T,
    const ull* __restrict__ A1, const ull* __restrict__ B1,
    const ull* __restrict__ A2, const ull* __restrict__ B2,
    bool v1, bool v2, ull neg1)
{
    ull u1[7], u2[7];
#pragma unroll
    for (int j = 0; j < 7; j++) {
        u1[j] = ffma2(B1[j], neg1, A1[j]);
        if (FUSED) u2[j] = ffma2(B2[j], neg1, A2[j]);
    }
    ull S1[7], S2[7];
    const ull z = pk2(0.f, 0.f);
#pragma unroll
    for (int k = 0; k < 7; k++) { S1[k] = z; if (FUSED) S2[k] = z; }
    int idx = 0;
#pragma unroll
    for (int jj = 0; jj < 7; jj++) {
        float lo1, hi1; upk2(u1[jj], lo1, hi1);
        ull bl1 = pk2(lo1, lo1), bh1 = pk2(hi1, hi1);
        ull bl2 = 0, bh2 = 0;
        if (FUSED) {
            float lo2, hi2; upk2(u2[jj], lo2, hi2);
            bl2 = pk2(lo2, lo2); bh2 = pk2(hi2, hi2);
        }
#pragma unroll
        for (int kk = 0; kk <= jj; kk++) {
            ull t = T[idx + kk];
            S1[kk] = ffma2(t, bl1, S1[kk]);
            if (FUSED) S2[kk] = ffma2(t, bl2, S2[kk]);
        }
#pragma unroll
        for (int kk = 0; kk <= jj; kk++) {
            ull t = T[idx + jj + 1 + kk];
            S1[kk] = ffma2(t, bh1, S1[kk]);
            if (FUSED) S2[kk] = ffma2(t, bh2, S2[kk]);
        }
        idx += 2 * (jj + 1);
    }
    float L1 = 0.f, L2 = 0.f;
#pragma unroll
    for (int k = 0; k < 7; k++) {
        float lo, hi;
        upk2(S1[k], lo, hi); L1 = fmaf(lo, lo, L1); L1 = fmaf(hi, hi, L1);
        if (FUSED) { upk2(S2[k], lo, hi); L2 = fmaf(lo, lo, L2); L2 = fmaf(hi, hi, L2); }
    }
    float r = v1 ? L1 : 0.f;
    if (FUSED) r += v2 ? L2 : 0.f;
    return r;
}

// ---------------------------------------------------------------------------

__device__ __forceinline__ void stage(uint32_t dstA, uint32_t dstB,
        const char* gA, const char* gB, int bytes, int tid) {
    const int n16 = bytes >> 4;
    for (int i = tid; i < n16; i += NTHR) {
        cp16(dstA + (i << 4), gA + ((size_t)i << 4));
        cp16(dstB + (i << 4), gB + ((size_t)i << 4));
    }
    if ((bytes & 8) && tid == 0) {
        cp8(dstA + (n16 << 4), gA + ((size_t)n16 << 4));
        cp8(dstB + (n16 << 4), gB + ((size_t)n16 << 4));
    }
}

__global__ __launch_bounds__(NTHR, 1)
void fused_kernel(const float* __restrict__ A, const float* __restrict__ Bv,
                  const int* __restrict__ ida, const int* __restrict__ idb,
                  const float* __restrict__ Wg, const float* __restrict__ Bg,
                  int N, float* __restrict__ out)
{
    extern __shared__ char smemraw[];
    Smem* S = (Smem*)smemraw;
    Pro*  P = &S->u.pro;
    const int tid = threadIdx.x, lane = tid & 31, wid = tid >> 5;
    const uint32_t smem_u = smem_u32(smemraw);
    const uint32_t buf_u  = smem_u + (uint32_t)offsetof(Smem, u);

    // ========== prologue phase 0: stage W (padded stride 65) / bias ==========
    for (int i = tid; i < 56 * 64; i += NTHR) {
        int r = i >> 6, c = i & 63;
        P->Wst[r * 65 + c] = Wg[i];
    }
    for (int i = tid; i < 4 * 64; i += NTHR) P->Bst[i] = Bg[i];
    if (tid < 16) S->count[tid] = 0;
    __syncthreads();

    // ========== phase 1: 10 expert Grams + Mc + cc (conflict-free) ==========
    for (int t = tid; t < 1960; t += NTHR) {
        int q = t / 196, r = t % 196, j = r / 14, k = r % 14;
        const float* vj = P->Wst + (PX[q] * 14 + j) * 65;
        const float* vk = P->Wst + (PY[q] * 14 + k) * 65;
        float s = 0.f;
#pragma unroll 8
        for (int c = 0; c < 64; c++) s = fmaf(vj[c], vk[c], s);
        P->Ge[q * 210 + j * 15 + k] = s;
    }
    for (int t = tid; t < 16 * 28 + 16; t += NTHR) {
        if (t < 16 * 28) {
            int p = t / 28, j = t % 28;
            int ea = p >> 2, eb = p & 3;
            if (ea == eb) continue;
            const float* vj = P->Wst + (((j < 14) ? ea : eb) * 14 + ((j < 14) ? j : j - 14)) * 65;
            const float* ba = P->Bst + ea * 64;
            const float* bb = P->Bst + eb * 64;
            float s = 0.f;
#pragma unroll 8
            for (int c = 0; c < 64; c++) s = fmaf(vj[c], ba[c] - bb[c], s);
            P->Mc[p][j] = (j < 14) ? s : -s;
        } else {
            int p = t - 16 * 28;
            int ea = p >> 2, eb = p & 3;
            float s = 0.f;
            if (ea != eb) {
                const float* ba = P->Bst + ea * 64;
                const float* bb = P->Bst + eb * 64;
                for (int c = 0; c < 64; c++) {
                    float d = ba[c] - bb[c];
                    s = fmaf(d, d, s);
                }
            }
            P->cc[p] = s;
        }
    }
    __syncthreads();

    // ========== phase 2: assemble pair matrices from expert Gram blocks ======
    for (int t = tid; t < 16 * 406; t += NTHR) {
        int p = t / 406, e = t % 406;
        int j = (int)((sqrtf(8.f * e + 1.f) - 1.f) * 0.5f);
        while ((j + 1) * (j + 2) / 2 <= e) j++;
        while (j * (j + 1) / 2 > e) j--;
        int k = e - j * (j + 1) / 2;
        int ea = p >> 2, eb = p & 3;
        if (ea == eb && j >= 14) continue;
        int xj = (j < 14) ? ea : eb, jj = (j < 14) ? j : j - 14;
        int xk = (k < 14) ? ea : eb, kk = (k < 14) ? k : k - 14;
        float v;
        if (xj <= xk) v = P->Ge[qidx(xj, xk) * 210 + jj * 15 + kk];
        else          v = P->Ge[qidx(xk, xj) * 210 + kk * 15 + jj];
        if ((j < 14) != (k < 14)) v = -v;
        P->C[p][j][k] = v;
    }
    __syncthreads();

    // ========== phase 3: per-warp Cholesky + solve + pack ==========
    {
        const int p = wid;
        float (*C)[29] = P->C[p];
        const int ea = p >> 2, eb = p & 3;
        const bool diag = (ea == eb);
        const int dim = diag ? 14 : 28;

        for (int k = 0; k < dim; k++) {
            float akk = C[k][k];
            __syncwarp();
            float sq = sqrtf(akk);
            float inv = 1.0f / sq;
            if (lane >= k && lane < dim) C[lane][k] = (lane == k) ? sq : C[lane][k] * inv;
            __syncwarp();
            if (lane > k && lane < dim) {
                float cjk = C[lane][k];
                for (int m = k + 1; m <= lane; m++) C[lane][m] -= cjk * C[m][k];
            }
            __syncwarp();
        }

        if (!diag) {
            float* dv = P->Mc[p];
            for (int k = 0; k < 28; k++) {
                if (lane == k) dv[k] = dv[k] / C[k][k];
                __syncwarp();
                if (lane > k && lane < 28) dv[lane] -= C[lane][k] * dv[k];
                __syncwarp();
            }
            float t = (lane < 28) ? dv[lane] * dv[lane] : 0.f;
#pragma unroll
            for (int off = 16; off; off >>= 1) t += __shfl_xor_sync(0xffffffffu, t, off);

            const int slot = p - p / 5 - 1;
            ull* T = S->tab + slot * OFF_ULL;
            if (lane == 0) ((float*)(S->tab + SPRIME_U))[p] = P->cc[p] - t;
            if (lane < 14) T[lane] = pk2(dv[2 * lane], dv[2 * lane + 1]);
            if (lane < 28) {
                int q = lane >> 1;
                ull* Tj = T + 14 + frow(lane);
                for (int kk2 = 0; kk2 <= q; kk2++) {
                    float lo = C[lane][2 * kk2];
                    float hi = (2 * kk2 + 1 <= lane) ? C[lane][2 * kk2 + 1] : 0.f;
                    Tj[kk2] = pk2(lo, hi);
                }
            }
        } else {
            ull* T = S->tab + DIAG_BASE + (p / 5) * DIAG_ULL;
            if (lane == 0) ((float*)(S->tab + SPRIME_U))[p] = 0.f;
            if (lane < 14) {
                int q = lane >> 1;
                ull* Tj = T + frow(lane);
                for (int kk2 = 0; kk2 <= q; kk2++) {
                    float lo = C[lane][2 * kk2];
                    float hi = (2 * kk2 + 1 <= lane) ? C[lane][2 * kk2 + 1] : 0.f;
                    Tj[kk2] = pk2(lo, hi);
                }
            }
        }
    }
    __syncthreads();              // prologue scratch dead; buffers may now be written

    // ========== main loop: double-buffered pipeline ==========
    const float* sS = (const float*)(S->tab + SPRIME_U);
    const ull neg1 = pk2(-1.f, -1.f);
    const int numTiles = (N + TILE - 1) / TILE;
    float acc = 0.f;
    int cur = 0;

    // prologue staging of first tile + its ids
    if (blockIdx.x < numTiles) {
        int cnt = min(TILE, N - blockIdx.x * TILE);
        stage(buf_u, buf_u + HALF_B,
              (const char*)A  + (size_t)blockIdx.x * TILE * ROW_B,
              (const char*)Bv + (size_t)blockIdx.x * TILE * ROW_B, cnt * ROW_B, tid);
    }
    asm volatile("cp.async.commit_group;");
    int cp0 = 0, cp1 = 0;
    if (blockIdx.x < numTiles) {
        int g0 = blockIdx.x * TILE + tid;
        int g1 = g0 + NTHR;
        if (g0 < N) cp0 = __ldg(ida + g0) * 4 + __ldg(idb + g0);
        if (g1 < N && tid + NTHR < TILE) cp1 = __ldg(ida + g1) * 4 + __ldg(idb + g1);
    }

    for (int tile = blockIdx.x; tile < numTiles; tile += gridDim.x) {
        const int cnt = min(TILE, N - tile * TILE);
        asm volatile("cp.async.wait_group 0;");
        __syncthreads();                                  // buffer ready, prev compute done

        // kick off next tile's copy into the other buffer
        const int nxt = tile + gridDim.x;
        const int nb = cur ^ 1;
        if (nxt < numTiles) {
            int ncnt = min(TILE, N - nxt * TILE);
            stage(buf_u + nb * BUF_SLOT, buf_u + nb * BUF_SLOT + HALF_B,
                  (const char*)A  + (size_t)nxt * TILE * ROW_B,
                  (const char*)Bv + (size_t)nxt * TILE * ROW_B, ncnt * ROW_B, tid);
        }
        asm volatile("cp.async.commit_group;");

        // histogram (ids already in regs)
        const bool act0 = tid < cnt;
        const bool act1 = tid + NTHR < cnt;
        if (act0) atomicAdd(&S->count[cp0], 1);
        if (act1) atomicAdd(&S->count[cp1], 1);

        // prefetch next tile's ids
        int np0 = 0, np1 = 0;
        if (nxt < numTiles) {
            int g0 = nxt * TILE + tid;
            int g1 = g0 + NTHR;
            if (g0 < N) np0 = __ldg(ida + g0) * 4 + __ldg(idb + g0);
            if (g1 < N && tid + NTHR < TILE) np1 = __ldg(ida + g1) * 4 + __ldg(idb + g1);
        }
        __syncthreads();

        // warp 0: prefix scan -> offsets + 64-row work items
        if (wid == 0) {
            int n = (lane < 16) ? S->count[lane] : 0;
            int nit = (n + 63) >> 6;
            int xs = n, xi = nit;
#pragma unroll
            for (int d = 1; d < 32; d <<= 1) {
                int ys = __shfl_up_sync(0xffffffffu, xs, d);
                int yi = __shfl_up_sync(0xffffffffu, xi, d);
                if (lane >= d) { xs += ys; xi += yi; }
            }
            int rowS = xs - n, itS = xi - nit;
            if (lane < 16) {
                S->ofs[lane] = rowS;
                for (int f = 0; f < nit; f++) {
                    S->wP[itS + f] = lane;
                    S->wO[itS + f] = rowS + f * 64;
                    S->wN[itS + f] = min(64, n - f * 64);
                }
            }
            if (lane == 15) S->num = xi;
        }
        __syncthreads();

        // scatter; clear counts for next tile
        if (act0) { int pos = atomicAdd(&S->ofs[cp0], 1); S->order[pos] = tid; }
        if (act1) { int pos = atomicAdd(&S->ofs[cp1], 1); S->order[pos] = tid + NTHR; }
        if (tid < 16) S->count[tid] = 0;
        __syncthreads();

        // compute: STATIC item striding (metadata prefetchable across items)
        const ull* bufA = (const ull*)(S->u.buf[cur]);
        const ull* bufB = bufA + TILE * 7;
        const int nItems = S->num;
        for (int it = wid; it < nItems; it += NWARP) {
            const int pp = S->wP[it], off = S->wO[it], n = S->wN[it];
            const bool v1 = lane < n;
            const bool v2 = 32 + lane < n;
            const int r1 = S->order[off + (v1 ? lane : 0)];
            const int r2 = S->order[off + (v2 ? 32 + lane : 0)];
            const ull* A1 = bufA + r1 * 7; const ull* B1 = bufB + r1 * 7;
            const ull* A2 = bufA + r2 * 7; const ull* B2 = bufB + r2 * 7;
            if (pp % 5 == 0) {
                const ull* T = S->tab + DIAG_BASE + (pp / 5) * DIAG_ULL;
                acc += (n > 32) ? eval_diag<true >(T, A1, B1, A2, B2, v1, v2, neg1)
                                : eval_diag<false>(T, A1, B1, A1, B1, v1, false, neg1);
            } else {
                const int slot = pp - pp / 5 - 1;
                const ull* T = S->tab + slot * OFF_ULL;
                const float sp = sS[pp];
                acc += (n > 32) ? eval_off<true >(T, sp, A1, B1, A2, B2, v1, v2)
                                : eval_off<false>(T, sp, A1, B1, A1, B1, v1, false);
            }
        }
        cp0 = np0; cp1 = np1; cur ^= 1;
    }

    // ---------- reduction + finalize (last CTA writes out, resets globals) ----
    __syncthreads();
#pragma unroll
    for (int off = 16; off; off >>= 1) acc += __shfl_xor_sync(0xffffffffu, acc, off);
    if (lane == 0) S->red[wid] = acc;
    __syncthreads();
    if (wid == 0) {
        float v = (lane < NWARP) ? S->red[lane] : 0.f;
#pragma unroll
        for (int off = 16; off; off >>= 1) v += __shfl_xor_sync(0xffffffffu, v, off);
        if (lane == 0) {
            atomicAdd(&g_sum, (double)v);
            __threadfence();
            int done = atomicAdd(&g_done, 1);
            if (done == (int)gridDim.x - 1) {
                double s = *((volatile double*)&g_sum);
                out[0] = (float)(s / ((double)N * 64.0));
                g_sum = 0.0;                 // reset for next graph replay
                g_done = 0;
            }
        }
    }
}

// ---------------------------------------------------------------------------

extern "C" void kernel_launch(void* const* d_in, const int* in_sizes, int n_in,
                              void* d_out, int out_size) {
    const float* A    = (const float*)d_in[0];   // (N,14)
    const float* B    = (const float*)d_in[1];   // (N,14)
    const int*   ia   = (const int*)d_in[2];     // (N,)
    const int*   ib   = (const int*)d_in[3];     // (N,)
    const float* W    = (const float*)d_in[4];   // (4,14,64)
    const float* bias = (const float*)d_in[5];   // (4,64)
    const int N = in_sizes[0] / 14;

    size_t smemBytes = sizeof(Smem) + 64;
    cudaFuncSetAttribute(fused_kernel, cudaFuncAttributeMaxDynamicSharedMemorySize,
                         (int)smemBytes);

    int sms = 148;
    cudaDeviceGetAttribute(&sms, cudaDevAttrMultiProcessorCount, 0);
    int numTiles = (N + TILE - 1) / TILE;
    int grid = numTiles < sms ? numTiles : sms;

    fused_kernel<<<grid, NTHR, smemBytes>>>(A, B, ia, ib, W, bias, N, (float*)d_out);
}

// round 15
// speedup vs baseline: 1.3133x; 1.3133x over previous
#include <cuda_runtime.h>
#include <cstdint>

// ---------------------------------------------------------------------------
// FrameConsistencyLoss, single persistent kernel.
//
// Prologue (per CTA, redundant, conflict-free, __noinline__ to isolate
// register allocation): stage W (stride-65 padded) + bias; 10 expert Grams;
// assemble 16 pair matrices M M^T; per-warp Cholesky + solve + packed table.
// Main loop (= R10's measured-103us loop): cp.async double-buffered 512-row
// tiles; histogram + counting sort by (ea,eb); warps process pair-uniform
// 64-row fused items with static striding; rows read from staged smem.
//
// L_row(off-diag) = || C^T w + d ||^2 + s'   (w=[a;b], C = chol(M M^T))
// L_row(diag)     = || C14^T (a-b) ||^2
// ---------------------------------------------------------------------------

#define TILE   512
#define NTHR   512
#define NWARP  16
#define MAXW   28

// table layout in ULLs
#define OFF_ULL   224
#define DIAG_BASE 2688
#define DIAG_ULL  56
#define SPRIME_U  2912
#define TAB_U     2920

#define ROW_B     56                      // bytes per row (14 floats)
#define HALF_B    (TILE * ROW_B)          // one array (A or B) per slot
#define BUF_SLOT  (2 * HALF_B)            // A then B

typedef unsigned long long ull;

__device__ double g_sum;
__device__ int    g_done;

__device__ const int PX[10] = {0,0,0,0,1,1,1,2,2,3};
__device__ const int PY[10] = {0,1,2,3,1,2,3,2,3,3};

__device__ __forceinline__ int qidx(int x, int y) {   // x <= y
    return 4 * x - (x * (x - 1)) / 2 + (y - x);
}

__device__ __forceinline__ ull pk2(float lo, float hi) {
    ull r; asm("mov.b64 %0, {%1,%2};" : "=l"(r) : "f"(lo), "f"(hi)); return r;
}
__device__ __forceinline__ void upk2(ull v, float& lo, float& hi) {
    asm("mov.b64 {%0,%1}, %2;" : "=f"(lo), "=f"(hi) : "l"(v));
}
__device__ __forceinline__ ull ffma2(ull a, ull b, ull c) {
    ull d; asm("fma.rn.f32x2 %0, %1, %2, %3;" : "=l"(d) : "l"(a), "l"(b), "l"(c)); return d;
}
__device__ __forceinline__ uint32_t smem_u32(const void* p) {
    uint32_t a;
    asm("{ .reg .u64 t; cvta.to.shared.u64 t, %1; cvt.u32.u64 %0, t; }" : "=r"(a) : "l"(p));
    return a;
}
__device__ __forceinline__ void cp16(uint32_t s, const void* g) {
    asm volatile("cp.async.cg.shared.global [%0], [%1], 16;" :: "r"(s), "l"(g));
}
__device__ __forceinline__ void cp8(uint32_t s, const void* g) {
    asm volatile("cp.async.ca.shared.global [%0], [%1], 8;" :: "r"(s), "l"(g));
}

__device__ __forceinline__ int frow(int j) {       // ulls in C-rows 0..j-1
    int q = j >> 1, r = j & 1;
    return j + q * (q - 1) + r * q;
}

struct Pro {
    float Wst[56 * 65];        // W rows, stride 65 (bank-conflict-free)
    float Bst[4 * 64];
    float Ge[10 * 14 * 15];    // expert Grams, row stride 15
    float C[16][28][29];       // assembled M M^T -> Cholesky scratch
    float Mc[16][28];
    float cc[16];
};

struct Smem {
    ull tab[TAB_U];
    union {
        Pro  pro;
        char buf[2][BUF_SLOT];
    } u;
    int   order[TILE];
    int   count[16];
    int   ofs[16];
    int   wP[MAXW], wO[MAXW], wN[MAXW];
    int   num;
    float red[NWARP];
};

// ---------------------------------------------------------------------------
// Prologue: build packed tables in smem. __noinline__ so its register
// pressure cannot perturb the main loop's allocation (R14 lesson: inlined
// prologue + static compute loop => 128 regs + spills).
// ---------------------------------------------------------------------------
__device__ __noinline__ void build_tables(Smem* S,
                                          const float* __restrict__ Wg,
                                          const float* __restrict__ Bg,
                                          int tid, int lane, int wid)
{
    Pro* P = &S->u.pro;

    // phase 0: stage W (padded stride 65) / bias
    for (int i = tid; i < 56 * 64; i += NTHR) {
        int r = i >> 6, c = i & 63;
        P->Wst[r * 65 + c] = Wg[i];
    }
    for (int i = tid; i < 4 * 64; i += NTHR) P->Bst[i] = Bg[i];
    __syncthreads();

    // phase 1: 10 expert Grams + Mc + cc (conflict-free)
    for (int t = tid; t < 1960; t += NTHR) {
        int q = t / 196, r = t % 196, j = r / 14, k = r % 14;
        const float* vj = P->Wst + (PX[q] * 14 + j) * 65;
        const float* vk = P->Wst + (PY[q] * 14 + k) * 65;
        float s = 0.f;
#pragma unroll 8
        for (int c = 0; c < 64; c++) s = fmaf(vj[c], vk[c], s);
        P->Ge[q * 210 + j * 15 + k] = s;
    }
    for (int t = tid; t < 16 * 28 + 16; t += NTHR) {
        if (t < 16 * 28) {
            int p = t / 28, j = t % 28;
            int ea = p >> 2, eb = p & 3;
            if (ea == eb) continue;
            const float* vj = P->Wst + (((j < 14) ? ea : eb) * 14 + ((j < 14) ? j : j - 14)) * 65;
            const float* ba = P->Bst + ea * 64;
            const float* bb = P->Bst + eb * 64;
            float s = 0.f;
#pragma unroll 8
            for (int c = 0; c < 64; c++) s = fmaf(vj[c], ba[c] - bb[c], s);
            P->Mc[p][j] = (j < 14) ? s : -s;
        } else {
            int p = t - 16 * 28;
            int ea = p >> 2, eb = p & 3;
            float s = 0.f;
            if (ea != eb) {
                const float* ba = P->Bst + ea * 64;
                const float* bb = P->Bst + eb * 64;
                for (int c = 0; c < 64; c++) {
                    float d = ba[c] - bb[c];
                    s = fmaf(d, d, s);
                }
            }
            P->cc[p] = s;
        }
    }
    __syncthreads();

    // phase 2: assemble pair matrices from expert Gram blocks
    for (int t = tid; t < 16 * 406; t += NTHR) {
        int p = t / 406, e = t % 406;
        int j = (int)((sqrtf(8.f * e + 1.f) - 1.f) * 0.5f);
        while ((j + 1) * (j + 2) / 2 <= e) j++;
        while (j * (j + 1) / 2 > e) j--;
        int k = e - j * (j + 1) / 2;
        int ea = p >> 2, eb = p & 3;
        if (ea == eb && j >= 14) continue;
        int xj = (j < 14) ? ea : eb, jj = (j < 14) ? j : j - 14;
        int xk = (k < 14) ? ea : eb, kk = (k < 14) ? k : k - 14;
        float v;
        if (xj <= xk) v = P->Ge[qidx(xj, xk) * 210 + jj * 15 + kk];
        else          v = P->Ge[qidx(xk, xj) * 210 + kk * 15 + jj];
        if ((j < 14) != (k < 14)) v = -v;
        P->C[p][j][k] = v;
    }
    __syncthreads();

    // phase 3: per-warp Cholesky + solve + pack
    {
        const int p = wid;
        float (*C)[29] = P->C[p];
        const int ea = p >> 2, eb = p & 3;
        const bool diag = (ea == eb);
        const int dim = diag ? 14 : 28;

        for (int k = 0; k < dim; k++) {
            float akk = C[k][k];
            __syncwarp();
            float sq = sqrtf(akk);
            float inv = 1.0f / sq;
            if (lane >= k && lane < dim) C[lane][k] = (lane == k) ? sq : C[lane][k] * inv;
            __syncwarp();
            if (lane > k && lane < dim) {
                float cjk = C[lane][k];
                for (int m = k + 1; m <= lane; m++) C[lane][m] -= cjk * C[m][k];
            }
            __syncwarp();
        }

        if (!diag) {
            float* dv = P->Mc[p];
            for (int k = 0; k < 28; k++) {
                if (lane == k) dv[k] = dv[k] / C[k][k];
                __syncwarp();
                if (lane > k && lane < 28) dv[lane] -= C[lane][k] * dv[k];
                __syncwarp();
            }
            float t = (lane < 28) ? dv[lane] * dv[lane] : 0.f;
#pragma unroll
            for (int off = 16; off; off >>= 1) t += __shfl_xor_sync(0xffffffffu, t, off);

            const int slot = p - p / 5 - 1;
            ull* T = S->tab + slot * OFF_ULL;
            if (lane == 0) ((float*)(S->tab + SPRIME_U))[p] = P->cc[p] - t;
            if (lane < 14) T[lane] = pk2(dv[2 * lane], dv[2 * lane + 1]);
            if (lane < 28) {
                int q = lane >> 1;
                ull* Tj = T + 14 + frow(lane);
                for (int kk2 = 0; kk2 <= q; kk2++) {
                    float lo = C[lane][2 * kk2];
                    float hi = (2 * kk2 + 1 <= lane) ? C[lane][2 * kk2 + 1] : 0.f;
                    Tj[kk2] = pk2(lo, hi);
                }
            }
        } else {
            ull* T = S->tab + DIAG_BASE + (p / 5) * DIAG_ULL;
            if (lane == 0) ((float*)(S->tab + SPRIME_U))[p] = 0.f;
            if (lane < 14) {
                int q = lane >> 1;
                ull* Tj = T + frow(lane);
                for (int kk2 = 0; kk2 <= q; kk2++) {
                    float lo = C[lane][2 * kk2];
                    float hi = (2 * kk2 + 1 <= lane) ? C[lane][2 * kk2 + 1] : 0.f;
                    Tj[kk2] = pk2(lo, hi);
                }
            }
        }
    }
}

// ---------------------------------------------------------------------------
// evaluation (pack-over-k; fused variant shares table LDS across 2 row sets)
// ---------------------------------------------------------------------------
template<bool FUSED>
__device__ __forceinline__ float eval_off(const ull* __restrict__ T, float sp,
    const ull* __restrict__ A1, const ull* __restrict__ B1,
    const ull* __restrict__ A2, const ull* __restrict__ B2,
    bool v1, bool v2)
{
    ull S1[14], S2[14];
#pragma unroll
    for (int k = 0; k < 14; k++) { S1[k] = T[k]; if (FUSED) S2[k] = T[k]; }
    int idx = 14;
#pragma unroll
    for (int jj = 0; jj < 14; jj++) {
        ull w1 = (jj < 7) ? A1[jj] : B1[jj - 7];
        float lo1, hi1; upk2(w1, lo1, hi1);
        ull bl1 = pk2(lo1, lo1), bh1 = pk2(hi1, hi1);
        ull bl2 = 0, bh2 = 0;
        if (FUSED) {
            ull w2 = (jj < 7) ? A2[jj] : B2[jj - 7];
            float lo2, hi2; upk2(w2, lo2, hi2);
            bl2 = pk2(lo2, lo2); bh2 = pk2(hi2, hi2);
        }
#pragma unroll
        for (int kk = 0; kk <= jj; kk++) {
            ull t = T[idx + kk];
            S1[kk] = ffma2(t, bl1, S1[kk]);
            if (FUSED) S2[kk] = ffma2(t, bl2, S2[kk]);
        }
#pragma unroll
        for (int kk = 0; kk <= jj; kk++) {
            ull t = T[idx + jj + 1 + kk];
            S1[kk] = ffma2(t, bh1, S1[kk]);
            if (FUSED) S2[kk] = ffma2(t, bh2, S2[kk]);
        }
        idx += 2 * (jj + 1);
    }
    float L1 = sp, L2 = sp;
#pragma unroll
    for (int k = 0; k < 14; k++) {
        float lo, hi;
        upk2(S1[k], lo, hi); L1 = fmaf(lo, lo, L1); L1 = fmaf(hi, hi, L1);
        if (FUSED) { upk2(S2[k], lo, hi); L2 = fmaf(lo, lo, L2); L2 = fmaf(hi, hi, L2); }
    }
    float r = v1 ? L1 : 0.f;
    if (FUSED) r += v2 ? L2 : 0.f;
    return r;
}

template<bool FUSED>
__device__ __forceinline__ float eval_diag(const ull* __restrict__ T,
    const ull* __restrict__ A1, const ull* __restrict__ B1,
    const ull* __restrict__ A2, const ull* __restrict__ B2,
    bool v1, bool v2, ull neg1)
{
    ull u1[7], u2[7];
#pragma unroll
    for (int j = 0; j < 7; j++) {
        u1[j] = ffma2(B1[j], neg1, A1[j]);
        if (FUSED) u2[j] = ffma2(B2[j], neg1, A2[j]);
    }
    ull S1[7], S2[7];
    const ull z = pk2(0.f, 0.f);
#pragma unroll
    for (int k = 0; k < 7; k++) { S1[k] = z; if (FUSED) S2[k] = z; }
    int idx = 0;
#pragma unroll
    for (int jj = 0; jj < 7; jj++) {
        float lo1, hi1; upk2(u1[jj], lo1, hi1);
        ull bl1 = pk2(lo1, lo1), bh1 = pk2(hi1, hi1);
        ull bl2 = 0, bh2 = 0;
        if (FUSED) {
            float lo2, hi2; upk2(u2[jj], lo2, hi2);
            bl2 = pk2(lo2, lo2); bh2 = pk2(hi2, hi2);
        }
#pragma unroll
        for (int kk = 0; kk <= jj; kk++) {
            ull t = T[idx + kk];
            S1[kk] = ffma2(t, bl1, S1[kk]);
            if (FUSED) S2[kk] = ffma2(t, bl2, S2[kk]);
        }
#pragma unroll
        for (int kk = 0; kk <= jj; kk++) {
            ull t = T[idx + jj + 1 + kk];
            S1[kk] = ffma2(t, bh1, S1[kk]);
            if (FUSED) S2[kk] = ffma2(t, bh2, S2[kk]);
        }
        idx += 2 * (jj + 1);
    }
    float L1 = 0.f, L2 = 0.f;
#pragma unroll
    for (int k = 0; k < 7; k++) {
        float lo, hi;
        upk2(S1[k], lo, hi); L1 = fmaf(lo, lo, L1); L1 = fmaf(hi, hi, L1);
        if (FUSED) { upk2(S2[k], lo, hi); L2 = fmaf(lo, lo, L2); L2 = fmaf(hi, hi, L2); }
    }
    float r = v1 ? L1 : 0.f;
    if (FUSED) r += v2 ? L2 : 0.f;
    return r;
}

// ---------------------------------------------------------------------------

__device__ __forceinline__ void stage(uint32_t dstA, uint32_t dstB,
        const char* gA, const char* gB, int bytes, int tid) {
    const int n16 = bytes >> 4;
    for (int i = tid; i < n16; i += NTHR) {
        cp16(dstA + (i << 4), gA + ((size_t)i << 4));
        cp16(dstB + (i << 4), gB + ((size_t)i << 4));
    }
    if ((bytes & 8) && tid == 0) {
        cp8(dstA + (n16 << 4), gA + ((size_t)n16 << 4));
        cp8(dstB + (n16 << 4), gB + ((size_t)n16 << 4));
    }
}

__global__ __launch_bounds__(NTHR, 1)
void fused_kernel(const float* __restrict__ A, const float* __restrict__ Bv,
                  const int* __restrict__ ida, const int* __restrict__ idb,
                  const float* __restrict__ Wg, const float* __restrict__ Bg,
                  int N, float* __restrict__ out)
{
    extern __shared__ char smemraw[];
    Smem* S = (Smem*)smemraw;
    const int tid = threadIdx.x, lane = tid & 31, wid = tid >> 5;
    const uint32_t smem_u = smem_u32(smemraw);
    const uint32_t buf_u  = smem_u + (uint32_t)offsetof(Smem, u);

    if (tid < 16) S->count[tid] = 0;
    build_tables(S, Wg, Bg, tid, lane, wid);
    __syncthreads();              // prologue scratch dead; buffers may now be written

    // ========== main loop: double-buffered pipeline (R10 structure) ==========
    const float* sS = (const float*)(S->tab + SPRIME_U);
    const ull neg1 = pk2(-1.f, -1.f);
    const int numTiles = (N + TILE - 1) / TILE;
    float acc = 0.f;
    int cur = 0;

    // prologue staging of first tile + its ids
    if (blockIdx.x < numTiles) {
        int cnt = min(TILE, N - blockIdx.x * TILE);
        stage(buf_u, buf_u + HALF_B,
              (const char*)A  + (size_t)blockIdx.x * TILE * ROW_B,
              (const char*)Bv + (size_t)blockIdx.x * TILE * ROW_B, cnt * ROW_B, tid);
    }
    asm volatile("cp.async.commit_group;");
    int cp0 = 0;
    if (blockIdx.x < numTiles) {
        int g0 = blockIdx.x * TILE + tid;
        if (g0 < N) cp0 = __ldg(ida + g0) * 4 + __ldg(idb + g0);
    }

    for (int tile = blockIdx.x; tile < numTiles; tile += gridDim.x) {
        const int cnt = min(TILE, N - tile * TILE);
        asm volatile("cp.async.wait_group 0;");
        __syncthreads();                                  // buffer ready, prev compute done

        // kick off next tile's copy into the other buffer
        const int nxt = tile + gridDim.x;
        const int nb = cur ^ 1;
        if (nxt < numTiles) {
            int ncnt = min(TILE, N - nxt * TILE);
            stage(buf_u + nb * BUF_SLOT, buf_u + nb * BUF_SLOT + HALF_B,
                  (const char*)A  + (size_t)nxt * TILE * ROW_B,
                  (const char*)Bv + (size_t)nxt * TILE * ROW_B, ncnt * ROW_B, tid);
        }
        asm volatile("cp.async.commit_group;");

        // histogram (ids already in regs)
        const bool act0 = tid < cnt;
        if (act0) atomicAdd(&S->count[cp0], 1);

        // prefetch next tile's ids
        int np0 = 0;
        if (nxt < numTiles) {
            int g0 = nxt * TILE + tid;
            if (g0 < N) np0 = __ldg(ida + g0) * 4 + __ldg(idb + g0);
        }
        __syncthreads();

        // warp 0: prefix scan -> offsets + 64-row work items
        if (wid == 0) {
            int n = (lane < 16) ? S->count[lane] : 0;
            int nit = (n + 63) >> 6;
            int xs = n, xi = nit;
#pragma unroll
            for (int d = 1; d < 32; d <<= 1) {
                int ys = __shfl_up_sync(0xffffffffu, xs, d);
                int yi = __shfl_up_sync(0xffffffffu, xi, d);
                if (lane >= d) { xs += ys; xi += yi; }
            }
            int rowS = xs - n, itS = xi - nit;
            if (lane < 16) {
                S->ofs[lane] = rowS;
                for (int f = 0; f < nit; f++) {
                    S->wP[itS + f] = lane;
                    S->wO[itS + f] = rowS + f * 64;
                    S->wN[itS + f] = min(64, n - f * 64);
                }
            }
            if (lane == 15) S->num = xi;
        }
        __syncthreads();

        // scatter; clear counts for next tile
        if (act0) { int pos = atomicAdd(&S->ofs[cp0], 1); S->order[pos] = tid; }
        if (tid < 16) S->count[tid] = 0;
        __syncthreads();

        // compute: static item striding, rows from staged smem
        const ull* bufA = (const ull*)(S->u.buf[cur]);
        const ull* bufB = bufA + TILE * 7;
        const int nItems = S->num;
        for (int it = wid; it < nItems; it += NWARP) {
            const int pp = S->wP[it], off = S->wO[it], n = S->wN[it];
            const bool v1 = lane < n;
            const bool v2 = 32 + lane < n;
            const int r1 = S->order[off + (v1 ? lane : 0)];
            const int r2 = S->order[off + (v2 ? 32 + lane : 0)];
            const ull* A1 = bufA + r1 * 7; const ull* B1 = bufB + r1 * 7;
            const ull* A2 = bufA + r2 * 7; const ull* B2 = bufB + r2 * 7;
            if (pp % 5 == 0) {
                const ull* T = S->tab + DIAG_BASE + (pp / 5) * DIAG_ULL;
                acc += (n > 32) ? eval_diag<true >(T, A1, B1, A2, B2, v1, v2, neg1)
                                : eval_diag<false>(T, A1, B1, A1, B1, v1, false, neg1);
            } else {
                const int slot = pp - pp / 5 - 1;
                const ull* T = S->tab + slot * OFF_ULL;
                const float sp = sS[pp];
                acc += (n > 32) ? eval_off<true >(T, sp, A1, B1, A2, B2, v1, v2)
                                : eval_off<false>(T, sp, A1, B1, A1, B1, v1, false);
            }
        }
        cp0 = np0; cur ^= 1;
    }

    // ---------- reduction + finalize (last CTA writes out, resets globals) ----
    __syncthreads();
#pragma unroll
    for (int off = 16; off; off >>= 1) acc += __shfl_xor_sync(0xffffffffu, acc, off);
    if (lane == 0) S->red[wid] = acc;
    __syncthreads();
    if (wid == 0) {
        float v = (lane < NWARP) ? S->red[lane] : 0.f;
#pragma unroll
        for (int off = 16; off; off >>= 1) v += __shfl_xor_sync(0xffffffffu, v, off);
        if (lane == 0) {
            atomicAdd(&g_sum, (double)v);
            __threadfence();
            int done = atomicAdd(&g_done, 1);
            if (done == (int)gridDim.x - 1) {
                double s = *((volatile double*)&g_sum);
                out[0] = (float)(s / ((double)N * 64.0));
                g_sum = 0.0;                 // reset for next graph replay
                g_done = 0;
            }
        }
    }
}

// ---------------------------------------------------------------------------

extern "C" void kernel_launch(void* const* d_in, const int* in_sizes, int n_in,
                              void* d_out, int out_size) {
    const float* A    = (const float*)d_in[0];   // (N,14)
    const float* B    = (const float*)d_in[1];   // (N,14)
    const int*   ia   = (const int*)d_in[2];     // (N,)
    const int*   ib   = (const int*)d_in[3];     // (N,)
    const float* W    = (const float*)d_in[4];   // (4,14,64)
    const float* bias = (const float*)d_in[5];   // (4,64)
    const int N = in_sizes[0] / 14;

    size_t smemBytes = sizeof(Smem) + 64;
    cudaFuncSetAttribute(fused_kernel, cudaFuncAttributeMaxDynamicSharedMemorySize,
                         (int)smemBytes);

    int sms = 148;
    cudaDeviceGetAttribute(&sms, cudaDevAttrMultiProcessorCount, 0);
    int numTiles = (N + TILE - 1) / TILE;
    int grid = numTiles < sms ? numTiles : sms;

    fused_kernel<<<grid, NTHR, smemBytes>>>(A, B, ia, ib, W, bias, N, (float*)d_out);
}

// round 16
// speedup vs baseline: 1.5029x; 1.1444x over previous
#include <cuda_runtime.h>
#include <cstdint>

// ---------------------------------------------------------------------------
// FrameConsistencyLoss, single persistent kernel.
//
// Table stream repacked for LDS.128: each aligned ulonglong2 holds the
// (even-row, odd-row) Cholesky pair for one accumulator column, so one
// 16-byte broadcast shared load feeds 2 (single) / 4 (fused) ffma2.
// Prologue (__noinline__, conflict-free) builds tables per CTA; main loop is
// the cp.async double-buffered 768-row pipeline with counting sort and
// static 64-row fused items.
//
// L_row(off-diag) = || C^T w + d ||^2 + s'   (w=[a;b], C = chol(M M^T))
// L_row(diag)     = || C14^T (a-b) ||^2
// ---------------------------------------------------------------------------

#define TILE   768
#define NTHR   512
#define NWARP  16
#define MAXW   28

// table layout in ULLs
#define OFF_ULL   224
#define DIAG_BASE 2688
#define DIAG_ULL  56
#define SPRIME_U  2912
#define TAB_U     2920

#define ROW_B     56                      // bytes per row (14 floats)
#define HALF_B    (TILE * ROW_B)          // one array (A or B) per slot
#define BUF_SLOT  (2 * HALF_B)            // A then B

typedef unsigned long long ull;

__device__ double g_sum;
__device__ int    g_done;

__device__ const int PX[10] = {0,0,0,0,1,1,1,2,2,3};
__device__ const int PY[10] = {0,1,2,3,1,2,3,2,3,3};

__device__ __forceinline__ int qidx(int x, int y) {   // x <= y
    return 4 * x - (x * (x - 1)) / 2 + (y - x);
}

__device__ __forceinline__ ull pk2(float lo, float hi) {
    ull r; asm("mov.b64 %0, {%1,%2};" : "=l"(r) : "f"(lo), "f"(hi)); return r;
}
__device__ __forceinline__ void upk2(ull v, float& lo, float& hi) {
    asm("mov.b64 {%0,%1}, %2;" : "=f"(lo), "=f"(hi) : "l"(v));
}
__device__ __forceinline__ ull ffma2(ull a, ull b, ull c) {
    ull d; asm("fma.rn.f32x2 %0, %1, %2, %3;" : "=l"(d) : "l"(a), "l"(b), "l"(c)); return d;
}
__device__ __forceinline__ uint32_t smem_u32(const void* p) {
    uint32_t a;
    asm("{ .reg .u64 t; cvta.to.shared.u64 t, %1; cvt.u32.u64 %0, t; }" : "=r"(a) : "l"(p));
    return a;
}
__device__ __forceinline__ void cp16(uint32_t s, const void* g) {
    asm volatile("cp.async.cg.shared.global [%0], [%1], 16;" :: "r"(s), "l"(g));
}
__device__ __forceinline__ void cp8(uint32_t s, const void* g) {
    asm volatile("cp.async.ca.shared.global [%0], [%1], 8;" :: "r"(s), "l"(g));
}

struct Pro {
    float Wst[56 * 65];        // W rows, stride 65 (bank-conflict-free)
    float Bst[4 * 64];
    float Ge[10 * 14 * 15];    // expert Grams, row stride 15
    float C[16][28][29];       // assembled M M^T -> Cholesky scratch
    float Mc[16][28];
    float cc[16];
};

struct Smem {
    ull tab[TAB_U];            // 16B-aligned (start of dynamic smem)
    union {
        Pro  pro;
        char buf[2][BUF_SLOT];
    } u;
    int   order[TILE];
    int   count[16];
    int   ofs[16];
    int   wP[MAXW], wO[MAXW], wN[MAXW];
    int   num;
    float red[NWARP];
};

// ---------------------------------------------------------------------------
// Prologue: build packed tables in smem. __noinline__ isolates its register
// pressure from the main loop (R14 lesson: inlining => 128 regs + spills).
//
// Packed layout (ULL units), off-diag pair slot (224 ulls):
//   [0..14)  d pairs: T[k] = (d_{2k}, d_{2k+1})
//   then for jj = 0..13 a block at 14 + jj(jj+1), size 2(jj+1):
//     position 14 + jj(jj+1) + 2*kk + r  =  (C[2jj+r][2kk], C[2jj+r][2kk+1])
//   -> each aligned ull2 [lo-row entry, hi-row entry] for column pair kk.
// Diag slot (56 ulls): same blocks without d, base jj(jj+1).
// ---------------------------------------------------------------------------
__device__ __noinline__ void build_tables(Smem* S,
                                          const float* __restrict__ Wg,
                                          const float* __restrict__ Bg,
                                          int tid, int lane, int wid)
{
    Pro* P = &S->u.pro;

    // phase 0: stage W (padded stride 65) / bias
    for (int i = tid; i < 56 * 64; i += NTHR) {
        int r = i >> 6, c = i & 63;
        P->Wst[r * 65 + c] = Wg[i];
    }
    for (int i = tid; i < 4 * 64; i += NTHR) P->Bst[i] = Bg[i];
    __syncthreads();

    // phase 1: 10 expert Grams + Mc + cc (conflict-free)
    for (int t = tid; t < 1960; t += NTHR) {
        int q = t / 196, r = t % 196, j = r / 14, k = r % 14;
        const float* vj = P->Wst + (PX[q] * 14 + j) * 65;
        const float* vk = P->Wst + (PY[q] * 14 + k) * 65;
        float s = 0.f;
#pragma unroll 8
        for (int c = 0; c < 64; c++) s = fmaf(vj[c], vk[c], s);
        P->Ge[q * 210 + j * 15 + k] = s;
    }
    for (int t = tid; t < 16 * 28 + 16; t += NTHR) {
        if (t < 16 * 28) {
            int p = t / 28, j = t % 28;
            int ea = p >> 2, eb = p & 3;
            if (ea == eb) continue;
            const float* vj = P->Wst + (((j < 14) ? ea : eb) * 14 + ((j < 14) ? j : j - 14)) * 65;
            const float* ba = P->Bst + ea * 64;
            const float* bb = P->Bst + eb * 64;
            float s = 0.f;
#pragma unroll 8
            for (int c = 0; c < 64; c++) s = fmaf(vj[c], ba[c] - bb[c], s);
            P->Mc[p][j] = (j < 14) ? s : -s;
        } else {
            int p = t - 16 * 28;
            int ea = p >> 2, eb = p & 3;
            float s = 0.f;
            if (ea != eb) {
                const float* ba = P->Bst + ea * 64;
                const float* bb = P->Bst + eb * 64;
                for (int c = 0; c < 64; c++) {
                    float d = ba[c] - bb[c];
                    s = fmaf(d, d, s);
                }
            }
            P->cc[p] = s;
        }
    }
    __syncthreads();

    // phase 2: assemble pair matrices from expert Gram blocks
    for (int t = tid; t < 16 * 406; t += NTHR) {
        int p = t / 406, e = t % 406;
        int j = (int)((sqrtf(8.f * e + 1.f) - 1.f) * 0.5f);
        while ((j + 1) * (j + 2) / 2 <= e) j++;
        while (j * (j + 1) / 2 > e) j--;
        int k = e - j * (j + 1) / 2;
        int ea = p >> 2, eb = p & 3;
        if (ea == eb && j >= 14) continue;
        int xj = (j < 14) ? ea : eb, jj = (j < 14) ? j : j - 14;
        int xk = (k < 14) ? ea : eb, kk = (k < 14) ? k : k - 14;
        float v;
        if (xj <= xk) v = P->Ge[qidx(xj, xk) * 210 + jj * 15 + kk];
        else          v = P->Ge[qidx(xk, xj) * 210 + kk * 15 + jj];
        if ((j < 14) != (k < 14)) v = -v;
        P->C[p][j][k] = v;
    }
    __syncthreads();

    // phase 3: per-warp Cholesky + solve + pack (interleaved ull2 layout)
    {
        const int p = wid;
        float (*C)[29] = P->C[p];
        const int ea = p >> 2, eb = p & 3;
        const bool diag = (ea == eb);
        const int dim = diag ? 14 : 28;

        for (int k = 0; k < dim; k++) {
            float akk = C[k][k];
            __syncwarp();
            float sq = sqrtf(akk);
            float inv = 1.0f / sq;
            if (lane >= k && lane < dim) C[lane][k] = (lane == k) ? sq : C[lane][k] * inv;
            __syncwarp();
            if (lane > k && lane < dim) {
                float cjk = C[lane][k];
                for (int m = k + 1; m <= lane; m++) C[lane][m] -= cjk * C[m][k];
            }
            __syncwarp();
        }

        if (!diag) {
            float* dv = P->Mc[p];
            for (int k = 0; k < 28; k++) {
                if (lane == k) dv[k] = dv[k] / C[k][k];
                __syncwarp();
                if (lane > k && lane < 28) dv[lane] -= C[lane][k] * dv[k];
                __syncwarp();
            }
            float t = (lane < 28) ? dv[lane] * dv[lane] : 0.f;
#pragma unroll
            for (int off = 16; off; off >>= 1) t += __shfl_xor_sync(0xffffffffu, t, off);

            const int slot = p - p / 5 - 1;
            ull* T = S->tab + slot * OFF_ULL;
            if (lane == 0) ((float*)(S->tab + SPRIME_U))[p] = P->cc[p] - t;
            if (lane < 14) T[lane] = pk2(dv[2 * lane], dv[2 * lane + 1]);
            if (lane < 28) {
                int q = lane >> 1, r = lane & 1;
                ull* Tb = T + 14 + q * (q + 1) + r;
                for (int kk2 = 0; kk2 <= q; kk2++) {
                    float lo = C[lane][2 * kk2];
                    float hi = (2 * kk2 + 1 <= lane) ? C[lane][2 * kk2 + 1] : 0.f;
                    Tb[2 * kk2] = pk2(lo, hi);
                }
            }
        } else {
            ull* T = S->tab + DIAG_BASE + (p / 5) * DIAG_ULL;
            if (lane == 0) ((float*)(S->tab + SPRIME_U))[p] = 0.f;
            if (lane < 14) {
                int q = lane >> 1, r = lane & 1;
                ull* Tb = T + q * (q + 1) + r;
                for (int kk2 = 0; kk2 <= q; kk2++) {
                    float lo = C[lane][2 * kk2];
                    float hi = (2 * kk2 + 1 <= lane) ? C[lane][2 * kk2 + 1] : 0.f;
                    Tb[2 * kk2] = pk2(lo, hi);
                }
            }
        }
    }
}

// ---------------------------------------------------------------------------
// evaluation: table consumed as aligned ulonglong2 (one LDS.128 feeds 2/4
// ffma2). Fused variant shares each load across 2 row sets.
// ---------------------------------------------------------------------------
template<bool FUSED>
__device__ __forceinline__ float eval_off(const ulonglong2* __restrict__ T2, float sp,
    const ull* __restrict__ A1, const ull* __restrict__ B1,
    const ull* __restrict__ A2, const ull* __restrict__ B2,
    bool v1, bool v2)
{
    ull S1[14], S2[14];
#pragma unroll
    for (int k2 = 0; k2 < 7; k2++) {
        ulonglong2 t = T2[k2];
        S1[2 * k2] = t.x; S1[2 * k2 + 1] = t.y;
        if (FUSED) { S2[2 * k2] = t.x; S2[2 * k2 + 1] = t.y; }
    }
    int base2 = 7;
#pragma unroll
    for (int jj = 0; jj < 14; jj++) {
        ull w1 = (jj < 7) ? A1[jj] : B1[jj - 7];
        float lo1, hi1; upk2(w1, lo1, hi1);
        ull bl1 = pk2(lo1, lo1), bh1 = pk2(hi1, hi1);
        ull bl2 = 0, bh2 = 0;
        if (FUSED) {
            ull w2 = (jj < 7) ? A2[jj] : B2[jj - 7];
            float lo2, hi2; upk2(w2, lo2, hi2);
            bl2 = pk2(lo2, lo2); bh2 = pk2(hi2, hi2);
        }
#pragma unroll
        for (int kk = 0; kk <= jj; kk++) {
            ulonglong2 t = T2[base2 + kk];
            S1[kk] = ffma2(t.x, bl1, S1[kk]);
            S1[kk] = ffma2(t.y, bh1, S1[kk]);
            if (FUSED) {
                S2[kk] = ffma2(t.x, bl2, S2[kk]);
                S2[kk] = ffma2(t.y, bh2, S2[kk]);
            }
        }
        base2 += jj + 1;
    }
    float L1 = sp, L2 = sp;
#pragma unroll
    for (int k = 0; k < 14; k++) {
        float lo, hi;
        upk2(S1[k], lo, hi); L1 = fmaf(lo, lo, L1); L1 = fmaf(hi, hi, L1);
        if (FUSED) { upk2(S2[k], lo, hi); L2 = fmaf(lo, lo, L2); L2 = fmaf(hi, hi, L2); }
    }
    float r = v1 ? L1 : 0.f;
    if (FUSED) r += v2 ? L2 : 0.f;
    return r;
}

template<bool FUSED>
__device__ __forceinline__ float eval_diag(const ulonglong2* __restrict__ T2,
    const ull* __restrict__ A1, const ull* __restrict__ B1,
    const ull* __restrict__ A2, const ull* __restrict__ B2,
    bool v1, bool v2, ull neg1)
{
    ull u1[7], u2[7];
#pragma unroll
    for (int j = 0; j < 7; j++) {
        u1[j] = ffma2(B1[j], neg1, A1[j]);
        if (FUSED) u2[j] = ffma2(B2[j], neg1, A2[j]);
    }
    ull S1[7], S2[7];
    const ull z = 0;
#pragma unroll
    for (int k = 0; k < 7; k++) { S1[k] = z; if (FUSED) S2[k] = z; }
    int base2 = 0;
#pragma unroll
    for (int jj = 0; jj < 7; jj++) {
        float lo1, hi1; upk2(u1[jj], lo1, hi1);
        ull bl1 = pk2(lo1, lo1), bh1 = pk2(hi1, hi1);
        ull bl2 = 0, bh2 = 0;
        if (FUSED) {
            float lo2, hi2; upk2(u2[jj], lo2, hi2);
            bl2 = pk2(lo2, lo2); bh2 = pk2(hi2, hi2);
        }
#pragma unroll
        for (int kk = 0; kk <= jj; kk++) {
            ulonglong2 t = T2[base2 + kk];
            S1[kk] = ffma2(t.x, bl1, S1[kk]);
            S1[kk] = ffma2(t.y, bh1, S1[kk]);
            if (FUSED) {
                S2[kk] = ffma2(t.x, bl2, S2[kk]);
                S2[kk] = ffma2(t.y, bh2, S2[kk]);
            }
        }
        base2 += jj + 1;
    }
    float L1 = 0.f, L2 = 0.f;
#pragma unroll
    for (int k = 0; k < 7; k++) {
        float lo, hi;
        upk2(S1[k], lo, hi); L1 = fmaf(lo, lo, L1); L1 = fmaf(hi, hi, L1);
        if (FUSED) { upk2(S2[k], lo, hi); L2 = fmaf(lo, lo, L2); L2 = fmaf(hi, hi, L2); }
    }
    float r = v1 ? L1 : 0.f;
    if (FUSED) r += v2 ? L2 : 0.f;
    return r;
}

// ---------------------------------------------------------------------------

__device__ __forceinline__ void stage(uint32_t dstA, uint32_t dstB,
        const char* gA, const char* gB, int bytes, int tid) {
    const int n16 = bytes >> 4;
    for (int i = tid; i < n16; i += NTHR) {
        cp16(dstA + (i << 4), gA + ((size_t)i << 4));
        cp16(dstB + (i << 4), gB + ((size_t)i << 4));
    }
    if ((bytes & 8) && tid == 0) {
        cp8(dstA + (n16 << 4), gA + ((size_t)n16 << 4));
        cp8(dstB + (n16 << 4), gB + ((size_t)n16 << 4));
    }
}

__global__ __launch_bounds__(NTHR, 1)
void fused_kernel(const float* __restrict__ A, const float* __restrict__ Bv,
                  const int* __restrict__ ida, const int* __restrict__ idb,
                  const float* __restrict__ Wg, const float* __restrict__ Bg,
                  int N, float* __restrict__ out)
{
    extern __shared__ __align__(16) char smemraw[];
    Smem* S = (Smem*)smemraw;
    const int tid = threadIdx.x, lane = tid & 31, wid = tid >> 5;
    const uint32_t smem_u = smem_u32(smemraw);
    const uint32_t buf_u  = smem_u + (uint32_t)offsetof(Smem, u);

    if (tid < 16) S->count[tid] = 0;
    build_tables(S, Wg, Bg, tid, lane, wid);
    __syncthreads();              // prologue scratch dead; buffers may now be written

    // ========== main loop: double-buffered pipeline ==========
    const float* sS = (const float*)(S->tab + SPRIME_U);
    const ull neg1 = pk2(-1.f, -1.f);
    const int numTiles = (N + TILE - 1) / TILE;
    float acc = 0.f;
    int cur = 0;

    // prologue staging of first tile + its ids
    if (blockIdx.x < numTiles) {
        int cnt = min(TILE, N - blockIdx.x * TILE);
        stage(buf_u, buf_u + HALF_B,
              (const char*)A  + (size_t)blockIdx.x * TILE * ROW_B,
              (const char*)Bv + (size_t)blockIdx.x * TILE * ROW_B, cnt * ROW_B, tid);
    }
    asm volatile("cp.async.commit_group;");
    int cp0 = 0, cp1 = 0;
    if (blockIdx.x < numTiles) {
        int g0 = blockIdx.x * TILE + tid;
        int g1 = g0 + NTHR;
        if (g0 < N) cp0 = __ldg(ida + g0) * 4 + __ldg(idb + g0);
        if (g1 < N && tid + NTHR < TILE) cp1 = __ldg(ida + g1) * 4 + __ldg(idb + g1);
    }

    for (int tile = blockIdx.x; tile < numTiles; tile += gridDim.x) {
        const int cnt = min(TILE, N - tile * TILE);
        asm volatile("cp.async.wait_group 0;");
        __syncthreads();                                  // buffer ready, prev compute done

        // kick off next tile's copy into the other buffer
        const int nxt = tile + gridDim.x;
        const int nb = cur ^ 1;
        if (nxt < numTiles) {
            int ncnt = min(TILE, N - nxt * TILE);
            stage(buf_u + nb * BUF_SLOT, buf_u + nb * BUF_SLOT + HALF_B,
                  (const char*)A  + (size_t)nxt * TILE * ROW_B,
                  (const char*)Bv + (size_t)nxt * TILE * ROW_B, ncnt * ROW_B, tid);
        }
        asm volatile("cp.async.commit_group;");

        // histogram (ids already in regs)
        const bool act0 = tid < cnt;
        const bool act1 = tid + NTHR < cnt;
        if (act0) atomicAdd(&S->count[cp0], 1);
        if (act1) atomicAdd(&S->count[cp1], 1);

        // prefetch next tile's ids
        int np0 = 0, np1 = 0;
        if (nxt < numTiles) {
            int g0 = nxt * TILE + tid;
            int g1 = g0 + NTHR;
            if (g0 < N) np0 = __ldg(ida + g0) * 4 + __ldg(idb + g0);
            if (g1 < N && tid + NTHR < TILE) np1 = __ldg(ida + g1) * 4 + __ldg(idb + g1);
        }
        __syncthreads();

        // warp 0: prefix scan -> offsets + 64-row work items
        if (wid == 0) {
            int n = (lane < 16) ? S->count[lane] : 0;
            int nit = (n + 63) >> 6;
            int xs = n, xi = nit;
#pragma unroll
            for (int d = 1; d < 32; d <<= 1) {
                int ys = __shfl_up_sync(0xffffffffu, xs, d);
                int yi = __shfl_up_sync(0xffffffffu, xi, d);
                if (lane >= d) { xs += ys; xi += yi; }
            }
            int rowS = xs - n, itS = xi - nit;
            if (lane < 16) {
                S->ofs[lane] = rowS;
                for (int f = 0; f < nit; f++) {
                    S->wP[itS + f] = lane;
                    S->wO[itS + f] = rowS + f * 64;
                    S->wN[itS + f] = min(64, n - f * 64);
                }
            }
            if (lane == 15) S->num = xi;
        }
        __syncthreads();

        // scatter; clear counts for next tile
        if (act0) { int pos = atomicAdd(&S->ofs[cp0], 1); S->order[pos] = tid; }
        if (act1) { int pos = atomicAdd(&S->ofs[cp1], 1); S->order[pos] = tid + NTHR; }
        if (tid < 16) S->count[tid] = 0;
        __syncthreads();

        // compute: static item striding, rows from staged smem
        const ull* bufA = (const ull*)(S->u.buf[cur]);
        const ull* bufB = bufA + TILE * 7;
        const int nItems = S->num;
        for (int it = wid; it < nItems; it += NWARP) {
            const int pp = S->wP[it], off = S->wO[it], n = S->wN[it];
            const bool v1 = lane < n;
            const bool v2 = 32 + lane < n;
            const int r1 = S->order[off + (v1 ? lane : 0)];
            const int r2 = S->order[off + (v2 ? 32 + lane : 0)];
            const ull* A1 = bufA + r1 * 7; const ull* B1 = bufB + r1 * 7;
            const ull* A2 = bufA + r2 * 7; const ull* B2 = bufB + r2 * 7;
            if (pp % 5 == 0) {
                const ulonglong2* T2 =
                    (const ulonglong2*)(S->tab + DIAG_BASE + (pp / 5) * DIAG_ULL);
                acc += (n > 32) ? eval_diag<true >(T2, A1, B1, A2, B2, v1, v2, neg1)
                                : eval_diag<false>(T2, A1, B1, A1, B1, v1, false, neg1);
            } else {
                const int slot = pp - pp / 5 - 1;
                const ulonglong2* T2 = (const ulonglong2*)(S->tab + slot * OFF_ULL);
                const float sp = sS[pp];
                acc += (n > 32) ? eval_off<true >(T2, sp, A1, B1, A2, B2, v1, v2)
                                : eval_off<false>(T2, sp, A1, B1, A1, B1, v1, false);
            }
        }
        cp0 = np0; cp1 = np1; cur ^= 1;
    }

    // ---------- reduction + finalize (last CTA writes out, resets globals) ----
    __syncthreads();
#pragma unroll
    for (int off = 16; off; off >>= 1) acc += __shfl_xor_sync(0xffffffffu, acc, off);
    if (lane == 0) S->red[wid] = acc;
    __syncthreads();
    if (wid == 0) {
        float v = (lane < NWARP) ? S->red[lane] : 0.f;
#pragma unroll
        for (int off = 16; off; off >>= 1) v += __shfl_xor_sync(0xffffffffu, v, off);
        if (lane == 0) {
            atomicAdd(&g_sum, (double)v);
            __threadfence();
            int done = atomicAdd(&g_done, 1);
            if (done == (int)gridDim.x - 1) {
                double s = *((volatile double*)&g_sum);
                out[0] = (float)(s / ((double)N * 64.0));
                g_sum = 0.0;                 // reset for next graph replay
                g_done = 0;
            }
        }
    }
}

// ---------------------------------------------------------------------------

extern "C" void kernel_launch(void* const* d_in, const int* in_sizes, int n_in,
                              void* d_out, int out_size) {
    const float* A    = (const float*)d_in[0];   // (N,14)
    const float* B    = (const float*)d_in[1];   // (N,14)
    const int*   ia   = (const int*)d_in[2];     // (N,)
    const int*   ib   = (const int*)d_in[3];     // (N,)
    const float* W    = (const float*)d_in[4];   // (4,14,64)
    const float* bias = (const float*)d_in[5];   // (4,64)
    const int N = in_sizes[0] / 14;

    size_t smemBytes = sizeof(Smem) + 64;
    cudaFuncSetAttribute(fused_kernel, cudaFuncAttributeMaxDynamicSharedMemorySize,
                         (int)smemBytes);

    int sms = 148;
    cudaDeviceGetAttribute(&sms, cudaDevAttrMultiProcessorCount, 0);
    int numTiles = (N + TILE - 1) / TILE;
    int grid = numTiles < sms ? numTiles : sms;

    fused_kernel<<<grid, NTHR, smemBytes>>>(A, B, ia, ib, W, bias, N, (float*)d_out);
}

// round 17
// speedup vs baseline: 1.6195x; 1.0776x over previous
#include <cuda_runtime.h>
#include <cstdint>

// ---------------------------------------------------------------------------
// FrameConsistencyLoss, single persistent kernel.
//
// Off-diag quadform evaluated in TWO COLUMN-HALF PASSES (S[0..6] then
// S[7..13]) so only 7 ull accumulators per row set are live at a time —
// halves register pressure vs R16 and lets ptxas pipeline the LDS.128
// table stream. Table layout per off-diag slot (226 ulls):
//   [0..8)     dA pairs (7 + pad)
//   [8..162)   pass-A blocks: jj=0..13, min(jj+1,7) ull2 each (kk=0..6)
//   [162..170) dB pairs (7 + pad)
//   [170..226) pass-B blocks: jj=7..13, (jj-6) ull2 each (kk=7..13)
// Each ull2 = (row 2jj | row 2jj+1) entries for one column pair kk.
//
// L_row(off-diag) = || C^T w + d ||^2 + s'   (w=[a;b], C = chol(M M^T))
// L_row(diag)     = || C14^T (a-b) ||^2
// ---------------------------------------------------------------------------

#define TILE   832
#define NTHR   512
#define NWARP  16
#define MAXW   32

// table layout in ULLs
#define OFF_ULL   226
#define DIAG_BASE 2712                    // 12 * 226
#define DIAG_ULL  56
#define SPRIME_U  2936                    // DIAG_BASE + 4*56
#define TAB_U     2944

#define ROW_B     56                      // bytes per row (14 floats)
#define HALF_B    (TILE * ROW_B)          // one array (A or B) per slot
#define BUF_SLOT  (2 * HALF_B)            // A then B

typedef unsigned long long ull;

__device__ double g_sum;
__device__ int    g_done;

__device__ const int PX[10] = {0,0,0,0,1,1,1,2,2,3};
__device__ const int PY[10] = {0,1,2,3,1,2,3,2,3,3};

__device__ __forceinline__ int qidx(int x, int y) {   // x <= y
    return 4 * x - (x * (x - 1)) / 2 + (y - x);
}

__device__ __forceinline__ ull pk2(float lo, float hi) {
    ull r; asm("mov.b64 %0, {%1,%2};" : "=l"(r) : "f"(lo), "f"(hi)); return r;
}
__device__ __forceinline__ void upk2(ull v, float& lo, float& hi) {
    asm("mov.b64 {%0,%1}, %2;" : "=f"(lo), "=f"(hi) : "l"(v));
}
__device__ __forceinline__ ull ffma2(ull a, ull b, ull c) {
    ull d; asm("fma.rn.f32x2 %0, %1, %2, %3;" : "=l"(d) : "l"(a), "l"(b), "l"(c)); return d;
}
__device__ __forceinline__ uint32_t smem_u32(const void* p) {
    uint32_t a;
    asm("{ .reg .u64 t; cvta.to.shared.u64 t, %1; cvt.u32.u64 %0, t; }" : "=r"(a) : "l"(p));
    return a;
}
__device__ __forceinline__ void cp16(uint32_t s, const void* g) {
    asm volatile("cp.async.cg.shared.global [%0], [%1], 16;" :: "r"(s), "l"(g));
}
__device__ __forceinline__ void cp8(uint32_t s, const void* g) {
    asm volatile("cp.async.ca.shared.global [%0], [%1], 8;" :: "r"(s), "l"(g));
}

struct Pro {
    float Wst[56 * 65];        // W rows, stride 65 (bank-conflict-free)
    float Bst[4 * 64];
    float Ge[10 * 14 * 15];    // expert Grams, row stride 15
    float C[16][28][29];       // assembled M M^T -> Cholesky scratch
    float Mc[16][28];
    float cc[16];
};

struct Smem {
    ull tab[TAB_U];            // 16B-aligned (start of dynamic smem)
    union {
        Pro  pro;
        char buf[2][BUF_SLOT];
    } u;
    int   order[TILE];
    int   count[16];
    int   ofs[16];
    int   wP[MAXW], wO[MAXW], wN[MAXW];
    int   num;
    float red[NWARP];
};

// ---------------------------------------------------------------------------
// Prologue: build packed tables in smem. __noinline__ isolates its register
// pressure from the main loop.
// ---------------------------------------------------------------------------
__device__ __noinline__ void build_tables(Smem* S,
                                          const float* __restrict__ Wg,
                                          const float* __restrict__ Bg,
                                          int tid, int lane, int wid)
{
    Pro* P = &S->u.pro;

    // phase 0: stage W (padded stride 65) / bias
    for (int i = tid; i < 56 * 64; i += NTHR) {
        int r = i >> 6, c = i & 63;
        P->Wst[r * 65 + c] = Wg[i];
    }
    for (int i = tid; i < 4 * 64; i += NTHR) P->Bst[i] = Bg[i];
    __syncthreads();

    // phase 1: 10 expert Grams + Mc + cc (conflict-free)
    for (int t = tid; t < 1960; t += NTHR) {
        int q = t / 196, r = t % 196, j = r / 14, k = r % 14;
        const float* vj = P->Wst + (PX[q] * 14 + j) * 65;
        const float* vk = P->Wst + (PY[q] * 14 + k) * 65;
        float s = 0.f;
#pragma unroll 8
        for (int c = 0; c < 64; c++) s = fmaf(vj[c], vk[c], s);
        P->Ge[q * 210 + j * 15 + k] = s;
    }
    for (int t = tid; t < 16 * 28 + 16; t += NTHR) {
        if (t < 16 * 28) {
            int p = t / 28, j = t % 28;
            int ea = p >> 2, eb = p & 3;
            if (ea == eb) continue;
            const float* vj = P->Wst + (((j < 14) ? ea : eb) * 14 + ((j < 14) ? j : j - 14)) * 65;
            const float* ba = P->Bst + ea * 64;
            const float* bb = P->Bst + eb * 64;
            float s = 0.f;
#pragma unroll 8
            for (int c = 0; c < 64; c++) s = fmaf(vj[c], ba[c] - bb[c], s);
            P->Mc[p][j] = (j < 14) ? s : -s;
        } else {
            int p = t - 16 * 28;
            int ea = p >> 2, eb = p & 3;
            float s = 0.f;
            if (ea != eb) {
                const float* ba = P->Bst + ea * 64;
                const float* bb = P->Bst + eb * 64;
                for (int c = 0; c < 64; c++) {
                    float d = ba[c] - bb[c];
                    s = fmaf(d, d, s);
                }
            }
            P->cc[p] = s;
        }
    }
    __syncthreads();

    // phase 2: assemble pair matrices from expert Gram blocks
    for (int t = tid; t < 16 * 406; t += NTHR) {
        int p = t / 406, e = t % 406;
        int j = (int)((sqrtf(8.f * e + 1.f) - 1.f) * 0.5f);
        while ((j + 1) * (j + 2) / 2 <= e) j++;
        while (j * (j + 1) / 2 > e) j--;
        int k = e - j * (j + 1) / 2;
        int ea = p >> 2, eb = p & 3;
        if (ea == eb && j >= 14) continue;
        int xj = (j < 14) ? ea : eb, jj = (j < 14) ? j : j - 14;
        int xk = (k < 14) ? ea : eb, kk = (k < 14) ? k : k - 14;
        float v;
        if (xj <= xk) v = P->Ge[qidx(xj, xk) * 210 + jj * 15 + kk];
        else          v = P->Ge[qidx(xk, xj) * 210 + kk * 15 + jj];
        if ((j < 14) != (k < 14)) v = -v;
        P->C[p][j][k] = v;
    }
    __syncthreads();

    // phase 3: per-warp Cholesky + solve + pack (two-pass split layout)
    {
        const int p = wid;
        float (*C)[29] = P->C[p];
        const int ea = p >> 2, eb = p & 3;
        const bool diag = (ea == eb);
        const int dim = diag ? 14 : 28;

        for (int k = 0; k < dim; k++) {
            float akk = C[k][k];
            __syncwarp();
            float sq = sqrtf(akk);
            float inv = 1.0f / sq;
            if (lane >= k && lane < dim) C[lane][k] = (lane == k) ? sq : C[lane][k] * inv;
            __syncwarp();
            if (lane > k && lane < dim) {
                float cjk = C[lane][k];
                for (int m = k + 1; m <= lane; m++) C[lane][m] -= cjk * C[m][k];
            }
            __syncwarp();
        }

        if (!diag) {
            float* dv = P->Mc[p];
            for (int k = 0; k < 28; k++) {
                if (lane == k) dv[k] = dv[k] / C[k][k];
                __syncwarp();
                if (lane > k && lane < 28) dv[lane] -= C[lane][k] * dv[k];
                __syncwarp();
            }
            float t = (lane < 28) ? dv[lane] * dv[lane] : 0.f;
#pragma unroll
            for (int off = 16; off; off >>= 1) t += __shfl_xor_sync(0xffffffffu, t, off);

            const int slot = p - p / 5 - 1;
            ull* T = S->tab + slot * OFF_ULL;
            if (lane == 0) ((float*)(S->tab + SPRIME_U))[p] = P->cc[p] - t;
            // dA (ulls 0..7), dB (ulls 162..169), pads zero
            if (lane < 7)  T[lane] = pk2(dv[2 * lane], dv[2 * lane + 1]);
            if (lane == 7) T[7] = 0;
            if (lane >= 8 && lane < 15)
                T[162 + lane - 8] = pk2(dv[14 + 2 * (lane - 8)], dv[15 + 2 * (lane - 8)]);
            if (lane == 15) T[169] = 0;
            __syncwarp();
            if (lane < 28) {
                const int jj = lane >> 1, r = lane & 1;
                // pass A: kk = 0..min(jj,6)
                int offA = (jj <= 7) ? (jj * (jj + 1) / 2) : (28 + 7 * (jj - 7));
                ull* Ta = T + 8 + 2 * offA + r;
                int kmaxA = (jj < 6) ? jj : 6;
                for (int kk = 0; kk <= kmaxA; kk++) {
                    float lo = C[lane][2 * kk];
                    float hi = (2 * kk + 1 <= lane) ? C[lane][2 * kk + 1] : 0.f;
                    Ta[2 * kk] = pk2(lo, hi);
                }
                // pass B: kk = 7..jj (rows jj >= 7 only)
                if (jj >= 7) {
                    int offB = (jj - 7) * (jj - 6) / 2;
                    ull* Tb = T + 170 + 2 * offB + r;
                    for (int kk = 7; kk <= jj; kk++) {
                        float lo = C[lane][2 * kk];
                        float hi = (2 * kk + 1 <= lane) ? C[lane][2 * kk + 1] : 0.f;
                        Tb[2 * (kk - 7)] = pk2(lo, hi);
                    }
                }
            }
        } else {
            ull* T = S->tab + DIAG_BASE + (p / 5) * DIAG_ULL;
            if (lane == 0) ((float*)(S->tab + SPRIME_U))[p] = 0.f;
            if (lane < 14) {
                int q = lane >> 1, r = lane & 1;
                ull* Tb = T + q * (q + 1) + r;
                for (int kk2 = 0; kk2 <= q; kk2++) {
                    float lo = C[lane][2 * kk2];
                    float hi = (2 * kk2 + 1 <= lane) ? C[lane][2 * kk2 + 1] : 0.f;
                    Tb[2 * kk2] = pk2(lo, hi);
                }
            }
        }
    }
}

// ---------------------------------------------------------------------------
// evaluation: two column-half passes, 7 ull accumulators live per row set.
// ---------------------------------------------------------------------------
template<bool FUSED>
__device__ __forceinline__ float eval_off(const ulonglong2* __restrict__ T2, float sp,
    const ull* __restrict__ A1, const ull* __restrict__ B1,
    const ull* __restrict__ A2, const ull* __restrict__ B2,
    bool v1, bool v2)
{
    float L1 = sp, L2 = sp;
    // ---- pass A: column pairs kk = 0..6, rows jj = 0..13 ----
    {
        ull S1[7], S2[7];
#pragma unroll
        for (int k2 = 0; k2 < 3; k2++) {
            ulonglong2 t = T2[k2];
            S1[2 * k2] = t.x; S1[2 * k2 + 1] = t.y;
            if (FUSED) { S2[2 * k2] = t.x; S2[2 * k2 + 1] = t.y; }
        }
        { ulonglong2 t = T2[3]; S1[6] = t.x; if (FUSED) S2[6] = t.x; }
        int b2 = 4;
#pragma unroll
        for (int jj = 0; jj < 14; jj++) {
            ull w1 = (jj < 7) ? A1[jj] : B1[jj - 7];
            float lo1, hi1; upk2(w1, lo1, hi1);
            ull bl1 = pk2(lo1, lo1), bh1 = pk2(hi1, hi1);
            ull bl2 = 0, bh2 = 0;
            if (FUSED) {
                ull w2 = (jj < 7) ? A2[jj] : B2[jj - 7];
                float lo2, hi2; upk2(w2, lo2, hi2);
                bl2 = pk2(lo2, lo2); bh2 = pk2(hi2, hi2);
            }
            const int kmax = (jj < 6) ? jj : 6;
#pragma unroll
            for (int kk = 0; kk <= kmax; kk++) {
                ulonglong2 t = T2[b2 + kk];
                S1[kk] = ffma2(t.x, bl1, S1[kk]);
                S1[kk] = ffma2(t.y, bh1, S1[kk]);
                if (FUSED) {
                    S2[kk] = ffma2(t.x, bl2, S2[kk]);
                    S2[kk] = ffma2(t.y, bh2, S2[kk]);
                }
            }
            b2 += kmax + 1;
        }
#pragma unroll
        for (int k = 0; k < 7; k++) {
            float lo, hi;
            upk2(S1[k], lo, hi); L1 = fmaf(lo, lo, L1); L1 = fmaf(hi, hi, L1);
            if (FUSED) { upk2(S2[k], lo, hi); L2 = fmaf(lo, lo, L2); L2 = fmaf(hi, hi, L2); }
        }
    }
    // ---- pass B: column pairs kk = 7..13, rows jj = 7..13 ----
    {
        ull S1[7], S2[7];
#pragma unroll
        for (int k2 = 0; k2 < 3; k2++) {
            ulonglong2 t = T2[81 + k2];
            S1[2 * k2] = t.x; S1[2 * k2 + 1] = t.y;
            if (FUSED) { S2[2 * k2] = t.x; S2[2 * k2 + 1] = t.y; }
        }
        { ulonglong2 t = T2[84]; S1[6] = t.x; if (FUSED) S2[6] = t.x; }
        int b2 = 85;
#pragma unroll
        for (int jj = 7; jj < 14; jj++) {
            ull w1 = B1[jj - 7];
            float lo1, hi1; upk2(w1, lo1, hi1);
            ull bl1 = pk2(lo1, lo1), bh1 = pk2(hi1, hi1);
            ull bl2 = 0, bh2 = 0;
            if (FUSED) {
                ull w2 = B2[jj - 7];
                float lo2, hi2; upk2(w2, lo2, hi2);
                bl2 = pk2(lo2, lo2); bh2 = pk2(hi2, hi2);
            }
#pragma unroll
            for (int kk = 0; kk <= jj - 7; kk++) {
                ulonglong2 t = T2[b2 + kk];
                S1[kk] = ffma2(t.x, bl1, S1[kk]);
                S1[kk] = ffma2(t.y, bh1, S1[kk]);
                if (FUSED) {
                    S2[kk] = ffma2(t.x, bl2, S2[kk]);
                    S2[kk] = ffma2(t.y, bh2, S2[kk]);
                }
            }
            b2 += jj - 6;
        }
#pragma unroll
        for (int k = 0; k < 7; k++) {
            float lo, hi;
            upk2(S1[k], lo, hi); L1 = fmaf(lo, lo, L1); L1 = fmaf(hi, hi, L1);
            if (FUSED) { upk2(S2[k], lo, hi); L2 = fmaf(lo, lo, L2); L2 = fmaf(hi, hi, L2); }
        }
    }
    float r = v1 ? L1 : 0.f;
    if (FUSED) r += v2 ? L2 : 0.f;
    return r;
}

template<bool FUSED>
__device__ __forceinline__ float eval_diag(const ulonglong2* __restrict__ T2,
    const ull* __restrict__ A1, const ull* __restrict__ B1,
    const ull* __restrict__ A2, const ull* __restrict__ B2,
    bool v1, bool v2, ull neg1)
{
    ull u1[7], u2[7];
#pragma unroll
    for (int j = 0; j < 7; j++) {
        u1[j] = ffma2(B1[j], neg1, A1[j]);
        if (FUSED) u2[j] = ffma2(B2[j], neg1, A2[j]);
    }
    ull S1[7], S2[7];
    const ull z = 0;
#pragma unroll
    for (int k = 0; k < 7; k++) { S1[k] = z; if (FUSED) S2[k] = z; }
    int base2 = 0;
#pragma unroll
    for (int jj = 0; jj < 7; jj++) {
        float lo1, hi1; upk2(u1[jj], lo1, hi1);
        ull bl1 = pk2(lo1, lo1), bh1 = pk2(hi1, hi1);
        ull bl2 = 0, bh2 = 0;
        if (FUSED) {
            float lo2, hi2; upk2(u2[jj], lo2, hi2);
            bl2 = pk2(lo2, lo2); bh2 = pk2(hi2, hi2);
        }
#pragma unroll
        for (int kk = 0; kk <= jj; kk++) {
            ulonglong2 t = T2[base2 + kk];
            S1[kk] = ffma2(t.x, bl1, S1[kk]);
            S1[kk] = ffma2(t.y, bh1, S1[kk]);
            if (FUSED) {
                S2[kk] = ffma2(t.x, bl2, S2[kk]);
                S2[kk] = ffma2(t.y, bh2, S2[kk]);
            }
        }
        base2 += jj + 1;
    }
    float L1 = 0.f, L2 = 0.f;
#pragma unroll
    for (int k = 0; k < 7; k++) {
        float lo, hi;
        upk2(S1[k], lo, hi); L1 = fmaf(lo, lo, L1); L1 = fmaf(hi, hi, L1);
        if (FUSED) { upk2(S2[k], lo, hi); L2 = fmaf(lo, lo, L2); L2 = fmaf(hi, hi, L2); }
    }
    float r = v1 ? L1 : 0.f;
    if (FUSED) r += v2 ? L2 : 0.f;
    return r;
}

// ---------------------------------------------------------------------------

__device__ __forceinline__ void stage(uint32_t dstA, uint32_t dstB,
        const char* gA, const char* gB, int bytes, int tid) {
    const int n16 = bytes >> 4;
    for (int i = tid; i < n16; i += NTHR) {
        cp16(dstA + (i << 4), gA + ((size_t)i << 4));
        cp16(dstB + (i << 4), gB + ((size_t)i << 4));
    }
    if ((bytes & 8) && tid == 0) {
        cp8(dstA + (n16 << 4), gA + ((size_t)n16 << 4));
        cp8(dstB + (n16 << 4), gB + ((size_t)n16 << 4));
    }
}

__global__ __launch_bounds__(NTHR, 1)
void fused_kernel(const float* __restrict__ A, const float* __restrict__ Bv,
                  const int* __restrict__ ida, const int* __restrict__ idb,
                  const float* __restrict__ Wg, const float* __restrict__ Bg,
                  int N, float* __restrict__ out)
{
    extern __shared__ __align__(16) char smemraw[];
    Smem* S = (Smem*)smemraw;
    const int tid = threadIdx.x, lane = tid & 31, wid = tid >> 5;
    const uint32_t smem_u = smem_u32(smemraw);
    const uint32_t buf_u  = smem_u + (uint32_t)offsetof(Smem, u);

    if (tid < 16) S->count[tid] = 0;
    build_tables(S, Wg, Bg, tid, lane, wid);
    __syncthreads();              // prologue scratch dead; buffers may now be written

    // ========== main loop: double-buffered pipeline ==========
    const float* sS = (const float*)(S->tab + SPRIME_U);
    const ull neg1 = pk2(-1.f, -1.f);
    const int numTiles = (N + TILE - 1) / TILE;
    float acc = 0.f;
    int cur = 0;

    // prologue staging of first tile + its ids
    if (blockIdx.x < numTiles) {
        int cnt = min(TILE, N - blockIdx.x * TILE);
        stage(buf_u, buf_u + HALF_B,
              (const char*)A  + (size_t)blockIdx.x * TILE * ROW_B,
              (const char*)Bv + (size_t)blockIdx.x * TILE * ROW_B, cnt * ROW_B, tid);
    }
    asm volatile("cp.async.commit_group;");
    int cp0 = 0, cp1 = 0;
    if (blockIdx.x < numTiles) {
        int g0 = blockIdx.x * TILE + tid;
        int g1 = g0 + NTHR;
        if (g0 < N) cp0 = __ldg(ida + g0) * 4 + __ldg(idb + g0);
        if (g1 < N && tid + NTHR < TILE) cp1 = __ldg(ida + g1) * 4 + __ldg(idb + g1);
    }

    for (int tile = blockIdx.x; tile < numTiles; tile += gridDim.x) {
        const int cnt = min(TILE, N - tile * TILE);
        asm volatile("cp.async.wait_group 0;");
        __syncthreads();                                  // buffer ready, prev compute done

        // kick off next tile's copy into the other buffer
        const int nxt = tile + gridDim.x;
        const int nb = cur ^ 1;
        if (nxt < numTiles) {
            int ncnt = min(TILE, N - nxt * TILE);
            stage(buf_u + nb * BUF_SLOT, buf_u + nb * BUF_SLOT + HALF_B,
                  (const char*)A  + (size_t)nxt * TILE * ROW_B,
                  (const char*)Bv + (size_t)nxt * TILE * ROW_B, ncnt * ROW_B, tid);
        }
        asm volatile("cp.async.commit_group;");

        // histogram (ids already in regs)
        const bool act0 = tid < cnt;
        const bool act1 = tid + NTHR < cnt;
        if (act0) atomicAdd(&S->count[cp0], 1);
        if (act1) atomicAdd(&S->count[cp1], 1);

        // prefetch next tile's ids
        int np0 = 0, np1 = 0;
        if (nxt < numTiles) {
            int g0 = nxt * TILE + tid;
            int g1 = g0 + NTHR;
            if (g0 < N) np0 = __ldg(ida + g0) * 4 + __ldg(idb + g0);
            if (g1 < N && tid + NTHR < TILE) np1 = __ldg(ida + g1) * 4 + __ldg(idb + g1);
        }
        __syncthreads();

        // warp 0: prefix scan -> offsets + 64-row work items
        if (wid == 0) {
            int n = (lane < 16) ? S->count[lane] : 0;
            int nit = (n + 63) >> 6;
            int xs = n, xi = nit;
#pragma unroll
            for (int d = 1; d < 32; d <<= 1) {
                int ys = __shfl_up_sync(0xffffffffu, xs, d);
                int yi = __shfl_up_sync(0xffffffffu, xi, d);
                if (lane >= d) { xs += ys; xi += yi; }
            }
            int rowS = xs - n, itS = xi - nit;
            if (lane < 16) {
                S->ofs[lane] = rowS;
                for (int f = 0; f < nit; f++) {
                    S->wP[itS + f] = lane;
                    S->wO[itS + f] = rowS + f * 64;
                    S->wN[itS + f] = min(64, n - f * 64);
                }
            }
            if (lane == 15) S->num = xi;
        }
        __syncthreads();

        // scatter; clear counts for next tile
        if (act0) { int pos = atomicAdd(&S->ofs[cp0], 1); S->order[pos] = tid; }
        if (act1) { int pos = atomicAdd(&S->ofs[cp1], 1); S->order[pos] = tid + NTHR; }
        if (tid < 16) S->count[tid] = 0;
        __syncthreads();

        // compute: static item striding, rows from staged smem
        const ull* bufA = (const ull*)(S->u.buf[cur]);
        const ull* bufB = bufA + TILE * 7;
        const int nItems = S->num;
        for (int it = wid; it < nItems; it += NWARP) {
            const int pp = S->wP[it], off = S->wO[it], n = S->wN[it];
            const bool v1 = lane < n;
            const bool v2 = 32 + lane < n;
            const int r1 = S->order[off + (v1 ? lane : 0)];
            const int r2 = S->order[off + (v2 ? 32 + lane : 0)];
            const ull* A1 = bufA + r1 * 7; const ull* B1 = bufB + r1 * 7;
            const ull* A2 = bufA + r2 * 7; const ull* B2 = bufB + r2 * 7;
            if (pp % 5 == 0) {
                const ulonglong2* T2 =
                    (const ulonglong2*)(S->tab + DIAG_BASE + (pp / 5) * DIAG_ULL);
                acc += (n > 32) ? eval_diag<true >(T2, A1, B1, A2, B2, v1, v2, neg1)
                                : eval_diag<false>(T2, A1, B1, A1, B1, v1, false, neg1);
            } else {
                const int slot = pp - pp / 5 - 1;
                const ulonglong2* T2 = (const ulonglong2*)(S->tab + slot * OFF_ULL);
                const float sp = sS[pp];
                acc += (n > 32) ? eval_off<true >(T2, sp, A1, B1, A2, B2, v1, v2)
                                : eval_off<false>(T2, sp, A1, B1, A1, B1, v1, false);
            }
        }
        cp0 = np0; cp1 = np1; cur ^= 1;
    }

    // ---------- reduction + finalize (last CTA writes out, resets globals) ----
    __syncthreads();
#pragma unroll
    for (int off = 16; off; off >>= 1) acc += __shfl_xor_sync(0xffffffffu, acc, off);
    if (lane == 0) S->red[wid] = acc;
    __syncthreads();
    if (wid == 0) {
        float v = (lane < NWARP) ? S->red[lane] : 0.f;
#pragma unroll
        for (int off = 16; off; off >>= 1) v += __shfl_xor_sync(0xffffffffu, v, off);
        if (lane == 0) {
            atomicAdd(&g_sum, (double)v);
            __threadfence();
            int done = atomicAdd(&g_done, 1);
            if (done == (int)gridDim.x - 1) {
                double s = *((volatile double*)&g_sum);
                out[0] = (float)(s / ((double)N * 64.0));
                g_sum = 0.0;                 // reset for next graph replay
                g_done = 0;
            }
        }
    }
}

// ---------------------------------------------------------------------------

extern "C" void kernel_launch(void* const* d_in, const int* in_sizes, int n_in,
                              void* d_out, int out_size) {
    const float* A    = (const float*)d_in[0];   // (N,14)
    const float* B    = (const float*)d_in[1];   // (N,14)
    const int*   ia   = (const int*)d_in[2];     // (N,)
    const int*   ib   = (const int*)d_in[3];     // (N,)
    const float* W    = (const float*)d_in[4];   // (4,14,64)
    const float* bias = (const float*)d_in[5];   // (4,64)
    const int N = in_sizes[0] / 14;

    size_t smemBytes = sizeof(Smem) + 64;
    cudaFuncSetAttribute(fused_kernel, cudaFuncAttributeMaxDynamicSharedMemorySize,
                         (int)smemBytes);

    int sms = 148;
    cudaDeviceGetAttribute(&sms, cudaDevAttrMultiProcessorCount, 0);
    int numTiles = (N + TILE - 1) / TILE;
    int grid = numTiles < sms ? numTiles : sms;

    fused_kernel<<<grid, NTHR, smemBytes>>>(A, B, ia, ib, W, bias, N, (float*)d_out);
}